// round 14
// baseline (speedup 1.0000x reference)
#include <cuda_runtime.h>
#include <math.h>

#define N_ENT 100000
#define N_REL 64
#define E_DIM 64
#define KNB   32
#define BSZ   1024

typedef unsigned long long ull;

// Device scratch (no allocation allowed)
__device__ float  d_scale[N_ENT];            // per-entity normalization scale
__device__ float  d_RW[N_REL * E_DIM];       // RW[rel][f] = Rnorm[rel] . w1r[f]
__device__ float2 d_W2P[E_DIM * 32];         // d_W2P[f*32+q] = (w2[q][f], w2[q+32][f])

__device__ __forceinline__ float leaky(float x) { return x >= 0.f ? x : 0.2f * x; }

__device__ __forceinline__ ull ffma2(ull a, ull b, ull c) {
    ull d;
    asm("fma.rn.f32x2 %0, %1, %2, %3;" : "=l"(d) : "l"(a), "l"(b), "l"(c));
    return d;
}
__device__ __forceinline__ ull packdup(float x) {
    ull d;
    asm("mov.b64 %0, {%1, %1};" : "=l"(d) : "f"(x));
    return d;
}

// ---------------------------------------------------------------------------
// prep kernel: blocks [0, NB_NORM) compute per-entity scales with 4-row ILP;
// last block normalizes R, builds RW and pre-pairs W2.
// ---------------------------------------------------------------------------
#define ROWS_PER_BLK 64
#define NB_NORM ((N_ENT + ROWS_PER_BLK - 1) / ROWS_PER_BLK)

__global__ void __launch_bounds__(256) prep_kernel(const float* __restrict__ E,
                                                   const float* __restrict__ R,
                                                   const float* __restrict__ w1,
                                                   const float* __restrict__ w2) {
    int tid = threadIdx.x, w = tid >> 5, lane = tid & 31;

    if (blockIdx.x < NB_NORM) {
        int l = tid & 15;
        int rg = tid >> 4;
        int r0 = blockIdx.x * ROWS_PER_BLK + rg;
        float s[4] = {0.f, 0.f, 0.f, 0.f};
        #pragma unroll
        for (int k = 0; k < 4; k++) {
            int row = r0 + k * 16;
            if (row < N_ENT) {
                float4 v = ((const float4*)(E + (size_t)row * E_DIM))[l];
                s[k] = v.x * v.x + v.y * v.y + v.z * v.z + v.w * v.w;
            }
        }
        #pragma unroll
        for (int o = 8; o > 0; o >>= 1)
            #pragma unroll
            for (int k = 0; k < 4; k++) s[k] += __shfl_xor_sync(0xffffffffu, s[k], o);
        if (l == 0) {
            #pragma unroll
            for (int k = 0; k < 4; k++) {
                int row = r0 + k * 16;
                if (row < N_ENT) {
                    float n = sqrtf(s[k]);
                    d_scale[row] = (n > 1.0f) ? 1.0f / (n + 1e-7f) : 1.0f;
                }
            }
        }
        return;
    }

    // ---- prepRW block ----
    __shared__ float Rn[N_REL * E_DIM];       // 16 KB
    __shared__ float w1rT[E_DIM * 65];
    #pragma unroll
    for (int k = 0; k < 8; k++) {
        int row = w * 8 + k;
        float2 v = ((const float2*)(R + row * E_DIM))[lane];
        float ss = v.x * v.x + v.y * v.y;
        #pragma unroll
        for (int o = 16; o > 0; o >>= 1) ss += __shfl_xor_sync(0xffffffffu, ss, o);
        float n = sqrtf(ss);
        float sc = (n > 1.0f) ? 1.0f / (n + 1e-7f) : 1.0f;
        Rn[row * E_DIM + lane * 2]     = v.x * sc;
        Rn[row * E_DIM + lane * 2 + 1] = v.y * sc;
    }
    for (int i = tid; i < E_DIM * E_DIM; i += 256) {
        int f = i >> 6, e = i & 63;
        w1rT[e * 65 + f] = w1[f * 128 + 64 + e];
    }
    #pragma unroll
    for (int j = 0; j < 8; j++) {
        int i = tid + j * 256;               // i = f*32+q
        int f = i >> 5, q = i & 31;
        d_W2P[i] = make_float2(w2[q * E_DIM + f], w2[(q + 32) * E_DIM + f]);
    }
    __syncthreads();
    #pragma unroll
    for (int j = 0; j < 16; j++) {
        int i = tid + j * 256;
        int rel = i >> 6, f = i & 63;
        float s = 0.f;
        #pragma unroll
        for (int e = 0; e < E_DIM; e++) s += Rn[rel * E_DIM + e] * w1rT[e * 65 + f];
        d_RW[rel * E_DIM + f] = s;
    }
}

// ---------------------------------------------------------------------------
// Fused per-root kernel. One block (256 threads) per root. (256,4): 64-reg cap.
// Entries: 0..31 = hop-1 neighbors (query hWh), 32..95 = hop-2 rels (hWs).
// Score GEMM: hid staged PRE-DUPLICATED (float2(x,x)) in two f-halves of 32;
// accumulators carried across the pass barrier; thread (w,lane) owns
// o-pairs {w*4..w*4+3} x entries {lane, lane+32, lane+64}. No packdup in loop.
// big[] union (ordered by __syncthreads):
//   hidD (float2) [0..6208) pitch 97
//   -> scoreP [0..768)
//   -> comb (float2) [768..2816) + aggP [2816..3360) + part [3360..4448)
// ---------------------------------------------------------------------------
__global__ void __launch_bounds__(256, 4) fused_kernel(
        const int* __restrict__ entity_idx,
        const int* __restrict__ adj_e,
        const int* __restrict__ adj_r,
        const float* __restrict__ E,
        const float* __restrict__ w1,
        const float* __restrict__ w3,
        const float* __restrict__ wxw,
        const float* __restrict__ wxb,
        const float* __restrict__ wcw,
        const float* __restrict__ wcb,
        float* __restrict__ out) {
    int b = blockIdx.x;
    int tid = threadIdx.x, w = tid >> 5, lane = tid & 31;

    __shared__ float  t1[KNB * E_DIM];          // 8 KB
    __shared__ int    idx2[KNB * KNB];          // 4 KB: idx | (rel<<20)
    __shared__ float  big[6208];                // 24.8 KB union
    __shared__ float  eaAll[96];
    __shared__ float  hS[E_DIM], hsumS[E_DIM];
    __shared__ float  hWh[E_DIM], hWs[E_DIM];
    __shared__ float  aggS1[E_DIM], aggS2[E_DIM];
    __shared__ float  vS1[E_DIM], vS2[E_DIM];
    __shared__ int    ent1[KNB], rel1[KNB];
    __shared__ float  red8[8];
    __shared__ float  sS1, sS2;

    float2* hidD   = (float2*)big;              // [0..6208) as 3104 float2, pitch 97
    ull*    hidU   = (ull*)big;                 // same region, ull view
    float*  scoreP = big;                       // [0..768), 8*96
    float2* combV  = (float2*)(big + 768);      // [768..2816), 1024 float2
    float*  aggP   = big + 2816;                // [2816..3360), 8*68
    float*  part   = big + 3360;                // [3360..4448), 16*68

    int eidx = entity_idx[b];
    // ---- Phase A: root loads ----
    if (tid < KNB) {
        ent1[tid] = adj_e[eidx * KNB + tid];
        rel1[tid] = adj_r[eidx * KNB + tid];
    }
    if (tid < E_DIM) hS[tid] = E[(size_t)eidx * E_DIM + tid] * __ldg(&d_scale[eidx]);
    __syncthreads();

    // ---- Phase B: hop-2 packed indices + normalized t1 rows ----
    for (int i = tid; i < KNB * KNB; i += 256) {
        int e1 = ent1[i >> 5];
        int id = adj_e[e1 * KNB + (i & 31)];
        int rl = adj_r[e1 * KNB + (i & 31)];
        idx2[i] = id | (rl << 20);
    }
    for (int i = tid; i < KNB * E_DIM; i += 256) {
        int n = i >> 6, e = i & 63;
        int id = ent1[n];
        t1[i] = E[(size_t)id * E_DIM + e] * __ldg(&d_scale[id]);
    }
    __syncthreads();

    // ---- hsum ----
    if (tid < E_DIM) {
        float s = 0.f;
        #pragma unroll
        for (int n = 0; n < KNB; n++) s += t1[n * E_DIM + tid];
        hsumS[tid] = s;
    }
    __syncthreads();

    // ---- query projections ----
    #pragma unroll
    for (int k = 0; k < 16; k++) {
        int job = w * 16 + k;
        int f = job & 63;
        const float* q = (job < 64) ? hS : hsumS;
        float2 wv = ((const float2*)(w1 + f * 128))[lane];
        float p = wv.x * q[lane * 2] + wv.y * q[lane * 2 + 1];
        #pragma unroll
        for (int o = 16; o > 0; o >>= 1) p += __shfl_down_sync(0xffffffffu, p, o);
        if (lane == 0) { if (job < 64) hWh[f] = p; else hWs[f] = p; }
    }
    __syncthreads();

    // ---- score GEMM: two f-halves; hid staged duplicated; accums carried ----
    ull a[12];
    #pragma unroll
    for (int i = 0; i < 12; i++) a[i] = 0ull;
    const ulonglong2* W2q = (const ulonglong2*)d_W2P;  // [f*16 + q/2]
    const float4* RW4 = (const float4*)d_RW;

    #pragma unroll
    for (int p = 0; p < 2; p++) {
        // stage hidD[fl*97 + entry] = dup(relu(q[f] + RW[rel][f])), fl = f-32p
        // jobs: 96 entries x 8 local segs (4 f each) = 768; 3 per thread
        #pragma unroll
        for (int j = 0; j < 3; j++) {
            int job = j * 256 + tid;
            int entry = job >> 3, segL = job & 7;
            int rel = (entry < KNB) ? rel1[entry] : (entry - KNB);
            const float* qv = (entry < KNB) ? hWh : hWs;
            float4 rw = __ldg(&RW4[rel * 16 + p * 8 + segL]);
            int f0 = p * 32 + segL * 4;
            float x0 = qv[f0]     + rw.x;
            float x1 = qv[f0 + 1] + rw.y;
            float x2 = qv[f0 + 2] + rw.z;
            float x3 = qv[f0 + 3] + rw.w;
            x0 = x0 > 0.f ? x0 : 0.f;
            x1 = x1 > 0.f ? x1 : 0.f;
            x2 = x2 > 0.f ? x2 : 0.f;
            x3 = x3 > 0.f ? x3 : 0.f;
            int fl = segL * 4;
            hidD[(fl)     * 97 + entry] = make_float2(x0, x0);
            hidD[(fl + 1) * 97 + entry] = make_float2(x1, x1);
            hidD[(fl + 2) * 97 + entry] = make_float2(x2, x2);
            hidD[(fl + 3) * 97 + entry] = make_float2(x3, x3);
        }
        __syncthreads();
        #pragma unroll 8
        for (int fl = 0; fl < 32; fl++) {
            int f = p * 32 + fl;
            ulonglong2 wab = __ldg(&W2q[f * 16 + w * 2]);
            ull h0 = hidU[fl * 97 + lane];
            ull h1 = hidU[fl * 97 + lane + 32];
            ull h2 = hidU[fl * 97 + lane + 64];
            a[0]  = ffma2(wab.x, h0, a[0]);
            a[1]  = ffma2(wab.x, h1, a[1]);
            a[2]  = ffma2(wab.x, h2, a[2]);
            a[3]  = ffma2(wab.y, h0, a[3]);
            a[4]  = ffma2(wab.y, h1, a[4]);
            a[5]  = ffma2(wab.y, h2, a[5]);
            ulonglong2 wcd = __ldg(&W2q[f * 16 + w * 2 + 1]);
            a[6]  = ffma2(wcd.x, h0, a[6]);
            a[7]  = ffma2(wcd.x, h1, a[7]);
            a[8]  = ffma2(wcd.x, h2, a[8]);
            a[9]  = ffma2(wcd.y, h0, a[9]);
            a[10] = ffma2(wcd.y, h1, a[10]);
            a[11] = ffma2(wcd.y, h2, a[11]);
        }
        __syncthreads();   // hidD region reused next pass / by scoreP
    }

    // ---- relu + w3 dot ----
    float sPart0, sPart1, sPart2;
    {
        float w3v[4], w3u[4];
        #pragma unroll
        for (int q = 0; q < 4; q++) {
            int o = w * 4 + q;
            w3v[q] = __ldg(&w3[o]);
            w3u[q] = __ldg(&w3[o + 32]);
        }
        float sp[3];
        #pragma unroll
        for (int j = 0; j < 3; j++) {
            float s = 0.f;
            #pragma unroll
            for (int q = 0; q < 4; q++) {
                ull av = a[q * 3 + j];
                float g0 = __uint_as_float((unsigned)(av & 0xffffffffull));
                float g1 = __uint_as_float((unsigned)(av >> 32));
                g0 = g0 > 0.f ? g0 : 0.f;
                g1 = g1 > 0.f ? g1 : 0.f;
                s += w3v[q] * g0 + w3u[q] * g1;
            }
            sp[j] = s;
        }
        sPart0 = sp[0]; sPart1 = sp[1]; sPart2 = sp[2];
    }
    // entries for thread: lane, lane+32, lane+64
    scoreP[w * 96 + lane]      = sPart0;
    scoreP[w * 96 + lane + 32] = sPart1;
    scoreP[w * 96 + lane + 64] = sPart2;
    __syncthreads();
    if (tid < 96) {
        float c = 0.f;
        #pragma unroll
        for (int ww = 0; ww < 8; ww++) c += scoreP[ww * 96 + tid];
        eaAll[tid] = expf(1.f / (1.f + expf(-c)));
    }
    __syncthreads();

    // ---- comb pack: (idx_bits, ea*scale) per neighbor; S2 partials; sS1 ----
    {
        float sp = 0.f;
        #pragma unroll
        for (int j = 0; j < 4; j++) {
            int i = tid * 4 + j;
            int v = idx2[i];
            int rl = v >> 20, id = v & 0xFFFFF;
            float ea = eaAll[32 + rl];
            combV[i] = make_float2(__int_as_float(id), ea * __ldg(&d_scale[id]));
            sp += ea;
        }
        #pragma unroll
        for (int o = 16; o > 0; o >>= 1) sp += __shfl_down_sync(0xffffffffu, sp, o);
        if (lane == 0) red8[w] = sp;
        if (w == 0) {   // hop-1 softmax denominator in parallel
            float e1v = eaAll[lane];
            #pragma unroll
            for (int o = 16; o > 0; o >>= 1) e1v += __shfl_down_sync(0xffffffffu, e1v, o);
            if (lane == 0) sS1 = e1v;
        }
    }
    __syncthreads();
    if (tid == 0) {
        float s = 0.f;
        #pragma unroll
        for (int i = 0; i < 8; i++) s += red8[i];
        sS2 = s;
    }

    // ---- hop-2 weighted gather: unroll 8, f32x2 accumulation ----
    {
        const ulonglong2* E8 = (const ulonglong2*)E;
        int seg = tid & 15, r = tid >> 4;
        ull ga0 = 0ull, ga1 = 0ull;
        #pragma unroll
        for (int base = 0; base < KNB * KNB; base += 128) {
            float2 cs[8];
            ulonglong2 vs[8];
            #pragma unroll
            for (int u8 = 0; u8 < 8; u8++)
                cs[u8] = combV[base + u8 * 16 + r];
            #pragma unroll
            for (int u8 = 0; u8 < 8; u8++)
                vs[u8] = __ldg(&E8[(size_t)__float_as_int(cs[u8].x) * 16 + seg]);
            #pragma unroll
            for (int u8 = 0; u8 < 8; u8++) {
                ull wd = packdup(cs[u8].y);
                ga0 = ffma2(wd, vs[u8].x, ga0);
                ga1 = ffma2(wd, vs[u8].y, ga1);
            }
        }
        ull* pdst = (ull*)(part + r * 68);
        pdst[seg * 2]     = ga0;
        pdst[seg * 2 + 1] = ga1;
    }

    // ---- hop-1 aggregation partials: all 8 warps, 4 neighbors each ----
    {
        float a0 = 0.f, a1 = 0.f;
        #pragma unroll
        for (int k = 0; k < 4; k++) {
            int n = w * 4 + k;
            float ea = eaAll[n];
            a0 += ea * t1[n * E_DIM + lane];
            a1 += ea * t1[n * E_DIM + lane + 32];
        }
        aggP[w * 68 + lane]      = a0;
        aggP[w * 68 + lane + 32] = a1;
    }
    __syncthreads();

    // ---- merged agg phase: aggS1 (tid<64) and aggS2 (tid in [64,128)) ----
    if (tid < E_DIM) {
        float s = 0.f;
        #pragma unroll
        for (int ww = 0; ww < 8; ww++) s += aggP[ww * 68 + tid];
        aggS1[tid] = s / sS1;
    } else if (tid < 2 * E_DIM) {
        int e = tid - E_DIM;
        float s = 0.f;
        #pragma unroll
        for (int r = 0; r < 16; r++) s += part[r * 68 + e];
        aggS2[e] = s / sS2;
    }
    __syncthreads();

    // ---- merged vS phase: 16 jobs/warp (8 hop-1 + 8 hop-2) ----
    #pragma unroll
    for (int k = 0; k < 16; k++) {
        int o = w * 8 + (k & 7);
        const float* ag = (k < 8) ? aggS1 : aggS2;
        float2 wv = ((const float2*)(wxw + o * E_DIM))[lane];
        float p = wv.x * ag[lane * 2] + wv.y * ag[lane * 2 + 1];
        #pragma unroll
        for (int off = 16; off > 0; off >>= 1) p += __shfl_down_sync(0xffffffffu, p, off);
        if (lane == 0) {
            float v = leaky(p + wxb[o]);
            if (k < 8) vS1[o] = v; else vS2[o] = v;
        }
    }
    __syncthreads();

    // ---- merged output phase: 16 jobs/warp (emb1 + emb2) + h passthrough ----
    #pragma unroll
    for (int k = 0; k < 16; k++) {
        int o = w * 8 + (k & 7);
        const float* xa = (k < 8) ? hS : hsumS;
        const float* xb = (k < 8) ? vS1 : vS2;
        float4 wv = ((const float4*)(wcw + o * 128))[lane];
        int i0 = lane * 4;
        float x0 = (i0 < 64)     ? xa[i0]     : xb[i0 - 64];
        float x1 = (i0 + 1 < 64) ? xa[i0 + 1] : xb[i0 - 63];
        float x2 = (i0 + 2 < 64) ? xa[i0 + 2] : xb[i0 - 62];
        float x3 = (i0 + 3 < 64) ? xa[i0 + 3] : xb[i0 - 61];
        float p = wv.x * x0 + wv.y * x1 + wv.z * x2 + wv.w * x3;
        #pragma unroll
        for (int off = 16; off > 0; off >>= 1) p += __shfl_down_sync(0xffffffffu, p, off);
        if (lane == 0) {
            int col = (k < 8) ? (64 + o) : o;
            out[b * 192 + col] = leaky(p + wcb[o]);
        }
    }
    if (tid < E_DIM) out[b * 192 + 128 + tid] = hS[tid];
}

// ---------------------------------------------------------------------------
extern "C" void kernel_launch(void* const* d_in, const int* in_sizes, int n_in,
                              void* d_out, int out_size) {
    const int*   entity_idx = (const int*)d_in[0];
    const int*   adj_e      = (const int*)d_in[1];
    const int*   adj_r      = (const int*)d_in[2];
    const float* E          = (const float*)d_in[3];
    const float* R          = (const float*)d_in[4];
    const float* w1         = (const float*)d_in[5];
    const float* w2         = (const float*)d_in[6];
    const float* w3         = (const float*)d_in[7];
    const float* wxw        = (const float*)d_in[8];
    const float* wxb        = (const float*)d_in[9];
    const float* wcw        = (const float*)d_in[10];
    const float* wcb        = (const float*)d_in[11];
    float* out = (float*)d_out;

    prep_kernel<<<NB_NORM + 1, 256>>>(E, R, w1, w2);
    fused_kernel<<<BSZ, 256>>>(entity_idx, adj_e, adj_r, E, w1, w3,
                               wxw, wxb, wcw, wcb, out);
}

// round 15
// speedup vs baseline: 1.2368x; 1.2368x over previous
#include <cuda_runtime.h>
#include <math.h>

#define N_ENT 100000
#define N_REL 64
#define E_DIM 64
#define KNB   32
#define BSZ   1024

typedef unsigned long long ull;

// Device scratch (no allocation allowed)
__device__ float  d_scale[N_ENT];            // per-entity normalization scale
__device__ float  d_RW[N_REL * E_DIM];       // RW[rel][f] = Rnorm[rel] . w1r[f]
__device__ float2 d_W2P[E_DIM * 32];         // d_W2P[f*32+q] = (w2[q][f], w2[q+32][f])

__device__ __forceinline__ float leaky(float x) { return x >= 0.f ? x : 0.2f * x; }

__device__ __forceinline__ ull ffma2(ull a, ull b, ull c) {
    ull d;
    asm("fma.rn.f32x2 %0, %1, %2, %3;" : "=l"(d) : "l"(a), "l"(b), "l"(c));
    return d;
}
__device__ __forceinline__ ull packdup(float x) {
    ull d;
    asm("mov.b64 %0, {%1, %1};" : "=l"(d) : "f"(x));
    return d;
}

// ---------------------------------------------------------------------------
// prep kernel: blocks [0, NB_NORM) compute per-entity scales with 8-row ILP
// (MLP=8: 8 independent LDG.128 in flight per thread); last block normalizes
// R, builds RW and pre-pairs W2.
// ---------------------------------------------------------------------------
#define ROWS_PER_BLK 128
#define NB_NORM ((N_ENT + ROWS_PER_BLK - 1) / ROWS_PER_BLK)

__global__ void __launch_bounds__(256) prep_kernel(const float* __restrict__ E,
                                                   const float* __restrict__ R,
                                                   const float* __restrict__ w1,
                                                   const float* __restrict__ w2) {
    int tid = threadIdx.x, w = tid >> 5, lane = tid & 31;

    if (blockIdx.x < NB_NORM) {
        int l = tid & 15;
        int rg = tid >> 4;
        int r0 = blockIdx.x * ROWS_PER_BLK + rg;
        float s[8];
        float4 v[8];
        #pragma unroll
        for (int k = 0; k < 8; k++) {
            int row = r0 + k * 16;
            v[k] = make_float4(0.f, 0.f, 0.f, 0.f);
            if (row < N_ENT) v[k] = ((const float4*)(E + (size_t)row * E_DIM))[l];
        }
        #pragma unroll
        for (int k = 0; k < 8; k++)
            s[k] = v[k].x * v[k].x + v[k].y * v[k].y + v[k].z * v[k].z + v[k].w * v[k].w;
        #pragma unroll
        for (int o = 8; o > 0; o >>= 1)
            #pragma unroll
            for (int k = 0; k < 8; k++) s[k] += __shfl_xor_sync(0xffffffffu, s[k], o);
        if (l == 0) {
            #pragma unroll
            for (int k = 0; k < 8; k++) {
                int row = r0 + k * 16;
                if (row < N_ENT) {
                    float n = sqrtf(s[k]);
                    d_scale[row] = (n > 1.0f) ? 1.0f / (n + 1e-7f) : 1.0f;
                }
            }
        }
        return;
    }

    // ---- prepRW block ----
    __shared__ float Rn[N_REL * E_DIM];       // 16 KB
    __shared__ float w1rT[E_DIM * 65];
    #pragma unroll
    for (int k = 0; k < 8; k++) {
        int row = w * 8 + k;
        float2 v = ((const float2*)(R + row * E_DIM))[lane];
        float ss = v.x * v.x + v.y * v.y;
        #pragma unroll
        for (int o = 16; o > 0; o >>= 1) ss += __shfl_xor_sync(0xffffffffu, ss, o);
        float n = sqrtf(ss);
        float sc = (n > 1.0f) ? 1.0f / (n + 1e-7f) : 1.0f;
        Rn[row * E_DIM + lane * 2]     = v.x * sc;
        Rn[row * E_DIM + lane * 2 + 1] = v.y * sc;
    }
    for (int i = tid; i < E_DIM * E_DIM; i += 256) {
        int f = i >> 6, e = i & 63;
        w1rT[e * 65 + f] = w1[f * 128 + 64 + e];
    }
    #pragma unroll
    for (int j = 0; j < 8; j++) {
        int i = tid + j * 256;               // i = f*32+q
        int f = i >> 5, q = i & 31;
        d_W2P[i] = make_float2(w2[q * E_DIM + f], w2[(q + 32) * E_DIM + f]);
    }
    __syncthreads();
    #pragma unroll
    for (int j = 0; j < 16; j++) {
        int i = tid + j * 256;
        int rel = i >> 6, f = i & 63;
        float s = 0.f;
        #pragma unroll
        for (int e = 0; e < E_DIM; e++) s += Rn[rel * E_DIM + e] * w1rT[e * 65 + f];
        d_RW[rel * E_DIM + f] = s;
    }
}

// ---------------------------------------------------------------------------
// Fused per-root kernel (R13 configuration — best known). One block (256
// threads) per root. (256,4): 64-reg cap.
// Entries: 0..31 = hop-1 neighbors (query hWh), 32..95 = hop-2 rels (hWs).
// big[] union (ordered by __syncthreads):
//   hidAll [0..6208) pitch 97
//   -> scoreP [0..768)
//   -> comb (float2) [768..2816) + aggP [2816..3360) + part [3360..4448)
// Epilogues for hop-1/hop-2 merged: 3 phases, 2 barriers.
// ---------------------------------------------------------------------------
__global__ void __launch_bounds__(256, 4) fused_kernel(
        const int* __restrict__ entity_idx,
        const int* __restrict__ adj_e,
        const int* __restrict__ adj_r,
        const float* __restrict__ E,
        const float* __restrict__ w1,
        const float* __restrict__ w3,
        const float* __restrict__ wxw,
        const float* __restrict__ wxb,
        const float* __restrict__ wcw,
        const float* __restrict__ wcb,
        float* __restrict__ out) {
    int b = blockIdx.x;
    int tid = threadIdx.x, w = tid >> 5, lane = tid & 31;

    __shared__ float  t1[KNB * E_DIM];          // 8 KB
    __shared__ int    idx2[KNB * KNB];          // 4 KB: idx | (rel<<20)
    __shared__ float  big[6208];                // 24.8 KB union
    __shared__ float  eaAll[96];
    __shared__ float  hS[E_DIM], hsumS[E_DIM];
    __shared__ float  hWh[E_DIM], hWs[E_DIM];
    __shared__ float  aggS1[E_DIM], aggS2[E_DIM];
    __shared__ float  vS1[E_DIM], vS2[E_DIM];
    __shared__ int    ent1[KNB], rel1[KNB];
    __shared__ float  red8[8];
    __shared__ float  sS1, sS2;

    float*  hidAll = big;                       // [0..6208), pitch 97
    float*  scoreP = big;                       // [0..768), 8*96
    float2* combV  = (float2*)(big + 768);      // [768..2816), 1024 float2
    float*  aggP   = big + 2816;                // [2816..3360), 8*68
    float*  part   = big + 3360;                // [3360..4448), 16*68

    int eidx = entity_idx[b];
    // ---- Phase A: root loads ----
    if (tid < KNB) {
        ent1[tid] = adj_e[eidx * KNB + tid];
        rel1[tid] = adj_r[eidx * KNB + tid];
    }
    if (tid < E_DIM) hS[tid] = E[(size_t)eidx * E_DIM + tid] * __ldg(&d_scale[eidx]);
    __syncthreads();

    // ---- Phase B: hop-2 packed indices + normalized t1 rows ----
    for (int i = tid; i < KNB * KNB; i += 256) {
        int e1 = ent1[i >> 5];
        int id = adj_e[e1 * KNB + (i & 31)];
        int rl = adj_r[e1 * KNB + (i & 31)];
        idx2[i] = id | (rl << 20);
    }
    for (int i = tid; i < KNB * E_DIM; i += 256) {
        int n = i >> 6, e = i & 63;
        int id = ent1[n];
        t1[i] = E[(size_t)id * E_DIM + e] * __ldg(&d_scale[id]);
    }
    __syncthreads();

    // ---- hsum ----
    if (tid < E_DIM) {
        float s = 0.f;
        #pragma unroll
        for (int n = 0; n < KNB; n++) s += t1[n * E_DIM + tid];
        hsumS[tid] = s;
    }
    __syncthreads();

    // ---- query projections ----
    #pragma unroll
    for (int k = 0; k < 16; k++) {
        int job = w * 16 + k;
        int f = job & 63;
        const float* q = (job < 64) ? hS : hsumS;
        float2 wv = ((const float2*)(w1 + f * 128))[lane];
        float p = wv.x * q[lane * 2] + wv.y * q[lane * 2 + 1];
        #pragma unroll
        for (int o = 16; o > 0; o >>= 1) p += __shfl_down_sync(0xffffffffu, p, o);
        if (lane == 0) { if (job < 64) hWh[f] = p; else hWs[f] = p; }
    }
    __syncthreads();

    // ---- stage hidAll via float4 RW loads ----
    {
        const float4* RW4 = (const float4*)d_RW;
        #pragma unroll
        for (int j = 0; j < 6; j++) {
            int job = j * 256 + tid;
            int entry = job >> 4, seg = job & 15;
            int rel = (entry < KNB) ? rel1[entry] : (entry - KNB);
            const float* qv = (entry < KNB) ? hWh : hWs;
            float4 rw = __ldg(&RW4[rel * 16 + seg]);
            int f0 = seg * 4;
            float x0 = qv[f0]     + rw.x;
            float x1 = qv[f0 + 1] + rw.y;
            float x2 = qv[f0 + 2] + rw.z;
            float x3 = qv[f0 + 3] + rw.w;
            hidAll[(f0)     * 97 + entry] = x0 > 0.f ? x0 : 0.f;
            hidAll[(f0 + 1) * 97 + entry] = x1 > 0.f ? x1 : 0.f;
            hidAll[(f0 + 2) * 97 + entry] = x2 > 0.f ? x2 : 0.f;
            hidAll[(f0 + 3) * 97 + entry] = x3 > 0.f ? x3 : 0.f;
        }
    }
    __syncthreads();

    // ---- score GEMM: single pass, 12 packed accums, W2 via 2x LDG.128/f ----
    float sPart0, sPart1, sPart2;
    {
        ull a[12];
        #pragma unroll
        for (int i = 0; i < 12; i++) a[i] = 0ull;
        const ulonglong2* W2q = (const ulonglong2*)d_W2P;  // [f*16 + q/2]
        int e0 = lane * 3;
        #pragma unroll 8
        for (int f = 0; f < E_DIM; f++) {
            ulonglong2 wab = __ldg(&W2q[f * 16 + w * 2]);
            ull h0 = packdup(hidAll[f * 97 + e0]);
            ull h1 = packdup(hidAll[f * 97 + e0 + 1]);
            ull h2 = packdup(hidAll[f * 97 + e0 + 2]);
            a[0]  = ffma2(wab.x, h0, a[0]);
            a[1]  = ffma2(wab.x, h1, a[1]);
            a[2]  = ffma2(wab.x, h2, a[2]);
            a[3]  = ffma2(wab.y, h0, a[3]);
            a[4]  = ffma2(wab.y, h1, a[4]);
            a[5]  = ffma2(wab.y, h2, a[5]);
            ulonglong2 wcd = __ldg(&W2q[f * 16 + w * 2 + 1]);
            a[6]  = ffma2(wcd.x, h0, a[6]);
            a[7]  = ffma2(wcd.x, h1, a[7]);
            a[8]  = ffma2(wcd.x, h2, a[8]);
            a[9]  = ffma2(wcd.y, h0, a[9]);
            a[10] = ffma2(wcd.y, h1, a[10]);
            a[11] = ffma2(wcd.y, h2, a[11]);
        }
        float w3v[4], w3u[4];
        #pragma unroll
        for (int q = 0; q < 4; q++) {
            int o = w * 4 + q;
            w3v[q] = __ldg(&w3[o]);
            w3u[q] = __ldg(&w3[o + 32]);
        }
        float sp[3];
        #pragma unroll
        for (int j = 0; j < 3; j++) {
            float s = 0.f;
            #pragma unroll
            for (int q = 0; q < 4; q++) {
                ull av = a[q * 3 + j];
                float g0 = __uint_as_float((unsigned)(av & 0xffffffffull));
                float g1 = __uint_as_float((unsigned)(av >> 32));
                g0 = g0 > 0.f ? g0 : 0.f;
                g1 = g1 > 0.f ? g1 : 0.f;
                s += w3v[q] * g0 + w3u[q] * g1;
            }
            sp[j] = s;
        }
        sPart0 = sp[0]; sPart1 = sp[1]; sPart2 = sp[2];
    }
    __syncthreads();   // hidAll dead
    {
        int e0 = lane * 3;
        scoreP[w * 96 + e0]     = sPart0;
        scoreP[w * 96 + e0 + 1] = sPart1;
        scoreP[w * 96 + e0 + 2] = sPart2;
    }
    __syncthreads();
    if (tid < 96) {
        float c = 0.f;
        #pragma unroll
        for (int ww = 0; ww < 8; ww++) c += scoreP[ww * 96 + tid];
        eaAll[tid] = expf(1.f / (1.f + expf(-c)));
    }
    __syncthreads();

    // ---- comb pack: (idx_bits, ea*scale) per neighbor; S2 partials; sS1 ----
    {
        float sp = 0.f;
        #pragma unroll
        for (int j = 0; j < 4; j++) {
            int i = tid * 4 + j;
            int v = idx2[i];
            int rl = v >> 20, id = v & 0xFFFFF;
            float ea = eaAll[32 + rl];
            combV[i] = make_float2(__int_as_float(id), ea * __ldg(&d_scale[id]));
            sp += ea;
        }
        #pragma unroll
        for (int o = 16; o > 0; o >>= 1) sp += __shfl_down_sync(0xffffffffu, sp, o);
        if (lane == 0) red8[w] = sp;
        if (w == 0) {   // hop-1 softmax denominator in parallel
            float e1v = eaAll[lane];
            #pragma unroll
            for (int o = 16; o > 0; o >>= 1) e1v += __shfl_down_sync(0xffffffffu, e1v, o);
            if (lane == 0) sS1 = e1v;
        }
    }
    __syncthreads();
    if (tid == 0) {
        float s = 0.f;
        #pragma unroll
        for (int i = 0; i < 8; i++) s += red8[i];
        sS2 = s;
    }

    // ---- hop-2 weighted gather: unroll 8 (MLP=8), 1 LDS.64 + 1 LDG.128 each
    {
        const float4* E4 = (const float4*)E;
        int seg = tid & 15, r = tid >> 4;
        float4 gacc = make_float4(0.f, 0.f, 0.f, 0.f);
        #pragma unroll
        for (int base = 0; base < KNB * KNB; base += 128) {
            float2 cs[8];
            float4 vs[8];
            #pragma unroll
            for (int u8 = 0; u8 < 8; u8++)
                cs[u8] = combV[base + u8 * 16 + r];
            #pragma unroll
            for (int u8 = 0; u8 < 8; u8++)
                vs[u8] = __ldg(&E4[(size_t)__float_as_int(cs[u8].x) * 16 + seg]);
            #pragma unroll
            for (int u8 = 0; u8 < 8; u8++) {
                float wv = cs[u8].y;
                gacc.x += wv * vs[u8].x; gacc.y += wv * vs[u8].y;
                gacc.z += wv * vs[u8].z; gacc.w += wv * vs[u8].w;
            }
        }
        ((float4*)(part + r * 68))[seg] = gacc;
    }

    // ---- hop-1 aggregation partials: all 8 warps, 4 neighbors each ----
    {
        float a0 = 0.f, a1 = 0.f;
        #pragma unroll
        for (int k = 0; k < 4; k++) {
            int n = w * 4 + k;
            float ea = eaAll[n];
            a0 += ea * t1[n * E_DIM + lane];
            a1 += ea * t1[n * E_DIM + lane + 32];
        }
        aggP[w * 68 + lane]      = a0;
        aggP[w * 68 + lane + 32] = a1;
    }
    __syncthreads();

    // ---- merged agg phase: aggS1 (tid<64) and aggS2 (tid in [64,128)) ----
    if (tid < E_DIM) {
        float s = 0.f;
        #pragma unroll
        for (int ww = 0; ww < 8; ww++) s += aggP[ww * 68 + tid];
        aggS1[tid] = s / sS1;
    } else if (tid < 2 * E_DIM) {
        int e = tid - E_DIM;
        float s = 0.f;
        #pragma unroll
        for (int r = 0; r < 16; r++) s += part[r * 68 + e];
        aggS2[e] = s / sS2;
    }
    __syncthreads();

    // ---- merged vS phase: 16 jobs/warp (8 hop-1 + 8 hop-2) ----
    #pragma unroll
    for (int k = 0; k < 16; k++) {
        int o = w * 8 + (k & 7);
        const float* ag = (k < 8) ? aggS1 : aggS2;
        float2 wv = ((const float2*)(wxw + o * E_DIM))[lane];
        float p = wv.x * ag[lane * 2] + wv.y * ag[lane * 2 + 1];
        #pragma unroll
        for (int off = 16; off > 0; off >>= 1) p += __shfl_down_sync(0xffffffffu, p, off);
        if (lane == 0) {
            float v = leaky(p + wxb[o]);
            if (k < 8) vS1[o] = v; else vS2[o] = v;
        }
    }
    __syncthreads();

    // ---- merged output phase: 16 jobs/warp (emb1 + emb2) + h passthrough ----
    #pragma unroll
    for (int k = 0; k < 16; k++) {
        int o = w * 8 + (k & 7);
        const float* xa = (k < 8) ? hS : hsumS;
        const float* xb = (k < 8) ? vS1 : vS2;
        float4 wv = ((const float4*)(wcw + o * 128))[lane];
        int i0 = lane * 4;
        float x0 = (i0 < 64)     ? xa[i0]     : xb[i0 - 64];
        float x1 = (i0 + 1 < 64) ? xa[i0 + 1] : xb[i0 - 63];
        float x2 = (i0 + 2 < 64) ? xa[i0 + 2] : xb[i0 - 62];
        float x3 = (i0 + 3 < 64) ? xa[i0 + 3] : xb[i0 - 61];
        float p = wv.x * x0 + wv.y * x1 + wv.z * x2 + wv.w * x3;
        #pragma unroll
        for (int off = 16; off > 0; off >>= 1) p += __shfl_down_sync(0xffffffffu, p, off);
        if (lane == 0) {
            int col = (k < 8) ? (64 + o) : o;
            out[b * 192 + col] = leaky(p + wcb[o]);
        }
    }
    if (tid < E_DIM) out[b * 192 + 128 + tid] = hS[tid];
}

// ---------------------------------------------------------------------------
extern "C" void kernel_launch(void* const* d_in, const int* in_sizes, int n_in,
                              void* d_out, int out_size) {
    const int*   entity_idx = (const int*)d_in[0];
    const int*   adj_e      = (const int*)d_in[1];
    const int*   adj_r      = (const int*)d_in[2];
    const float* E          = (const float*)d_in[3];
    const float* R          = (const float*)d_in[4];
    const float* w1         = (const float*)d_in[5];
    const float* w2         = (const float*)d_in[6];
    const float* w3         = (const float*)d_in[7];
    const float* wxw        = (const float*)d_in[8];
    const float* wxb        = (const float*)d_in[9];
    const float* wcw        = (const float*)d_in[10];
    const float* wcb        = (const float*)d_in[11];
    float* out = (float*)d_out;

    prep_kernel<<<NB_NORM + 1, 256>>>(E, R, w1, w2);
    fused_kernel<<<BSZ, 256>>>(entity_idx, adj_e, adj_r, E, w1, w3,
                               wxw, wxb, wcw, wcb, out);
}